// round 15
// baseline (speedup 1.0000x reference)
#include <cuda_runtime.h>
#include <math.h>

#define BATCH 8
#define NPTS 2048
#define NTOT (BATCH*NPTS)
#define CH 128
#define KNN 16
#define HID 32
#define EPSV 1e-6f

typedef unsigned long long ull;

// ---------------- scratch (static device globals) ---------------------------
// SoA layout: [point][coord][128 channels]
__device__ float g_Q[NTOT*CH*3];
__device__ float g_K[NTOT*CH*3];
__device__ float g_U[NTOT*CH*3];
__device__ ull   g_Wt2[3*CH*CH];     // duplicated-packed weights [w][c][o] = (val,val)
__device__ int   g_idx[NTOT*KNN];
__device__ float g_dist[NTOT*KNN];
__device__ float g_qn[NTOT];
__device__ float g_kn[NTOT];

// ---------------- packed f32x2 helpers (Blackwell FFMA2) --------------------
__device__ __forceinline__ ull pack2(float lo, float hi) {
    ull r;
    asm("mov.b64 %0, {%1,%2};" : "=l"(r) : "f"(lo), "f"(hi));
    return r;
}
__device__ __forceinline__ void unpack2(ull v, float& lo, float& hi) {
    asm("mov.b64 {%0,%1}, %2;" : "=f"(lo), "=f"(hi) : "l"(v));
}
__device__ __forceinline__ ull fma2(ull a, ull b, ull c) {
    ull d;
    asm("fma.rn.f32x2 %0, %1, %2, %3;" : "=l"(d) : "l"(a), "l"(b), "l"(c));
    return d;
}
__device__ __forceinline__ void group_bar(int g) {
    asm volatile("bar.sync %0, 128;" :: "r"(g + 1) : "memory");
}
// monotone float->uint transform
__device__ __forceinline__ unsigned ford(float f) {
    unsigned u = __float_as_uint(f);
    return u ^ ((unsigned)(((int)u) >> 31) | 0x80000000u);
}

// ---------------- noop (launch-slot spacer so profiler captures attn) -------
__global__ void noop_kernel() {}

// ---------------- weight transpose + duplicate-pack --------------------------
__global__ void transpose_w_kernel(const float* __restrict__ Wq,
                                   const float* __restrict__ Wk,
                                   const float* __restrict__ Wu) {
    int i = blockIdx.x * 256 + threadIdx.x;       // i = o*128 + c
    if (i >= CH*CH) return;
    int o = i >> 7, c = i & 127;
    float wq = Wq[i], wk = Wk[i], wu = Wu[i];
    g_Wt2[0*CH*CH + c*CH + o] = pack2(wq, wq);
    g_Wt2[1*CH*CH + c*CH + o] = pack2(wk, wk);
    g_Wt2[2*CH*CH + c*CH + o] = pack2(wu, wu);
}

// ---------------- KNN: radix-select, 2 queries/block, bitonic tail ----------
__device__ __forceinline__ unsigned fkey(float ax, float ay, float az, int j,
                                         float qx, float qy, float qz,
                                         float qs, int q) {
    float sj  = ax*ax + ay*ay + az*az;
    float dot = qx*ax + qy*ay + qz*az;
    float d2  = (qs + sj) - 2.f*dot;
    if (j == q) d2 = INFINITY;
    return ford(d2);
}

// warp-0-of-group only: smallest bin with cum_incl >= target over 256 bins.
__device__ __forceinline__ void radix_scan(const unsigned* hist, int lane,
                                           unsigned target,
                                           unsigned* outB, unsigned* outLt) {
    unsigned c[8]; unsigned s = 0;
#pragma unroll
    for (int i = 0; i < 8; i++) { c[i] = hist[lane*8 + i]; s += c[i]; }
    unsigned pre = s;
#pragma unroll
    for (int d = 1; d < 32; d <<= 1) {
        unsigned o = __shfl_up_sync(0xffffffffu, pre, d);
        if (lane >= d) pre += o;
    }
    unsigned excl = pre - s;
    bool has = (excl < target) && (excl + s >= target);
    unsigned mask = __ballot_sync(0xffffffffu, has);
    int src = __ffs((int)mask) - 1;
    if (lane == src) {
        unsigned cum = excl, lt = excl; int bsel = lane*8;
#pragma unroll
        for (int i = 0; i < 8; i++) {
            if (cum < target) { bsel = lane*8 + i; lt = cum; cum += c[i]; }
        }
        *outB = (unsigned)bsel; *outLt = lt;
    }
}

__global__ __launch_bounds__(256) void knn_kernel(const float* __restrict__ x) {
    int tid  = threadIdx.x;
    int g    = tid >> 7;              // query group 0/1
    int gtid = tid & 127;
    int lane = tid & 31;
    int gw   = (tid >> 5) & 3;
    int n    = (blockIdx.x << 1) + g;
    int b    = n >> 11;
    int q    = n & 2047;
    const float* xb = x + (size_t)b * NPTS * 3;

    __shared__ unsigned hist[2][512];  // [g][pass1:0-255 | pass2:256-511]
    __shared__ ull cand[2][NPTS];
    __shared__ int scand[2];
    __shared__ unsigned sB1[2], sLt[2], sB2[2], sLt2[2];

    // zero both histogram buffers up front (4 entries/thread)
    hist[g][gtid] = 0; hist[g][gtid+128] = 0;
    hist[g][gtid+256] = 0; hist[g][gtid+384] = 0;
    if (gtid == 0) scand[g] = 0;

    float qx = xb[3*q+0], qy = xb[3*q+1], qz = xb[3*q+2];
    float qs = qx*qx + qy*qy + qz*qz;

    // 16 consecutive candidates per thread via 12 float4 loads (4 chunks)
    int j0 = gtid * 16;
    const float4* xp4 = reinterpret_cast<const float4*>(xb + (size_t)j0 * 3);
    unsigned fu[16];
#pragma unroll
    for (int ck = 0; ck < 4; ck++) {
        float4 P = xp4[ck*3+0], Qv = xp4[ck*3+1], R = xp4[ck*3+2];
        int jj = j0 + ck*4;
        fu[ck*4+0] = fkey(P.x, P.y, P.z,  jj+0, qx,qy,qz,qs,q);
        fu[ck*4+1] = fkey(P.w, Qv.x, Qv.y, jj+1, qx,qy,qz,qs,q);
        fu[ck*4+2] = fkey(Qv.z, Qv.w, R.x, jj+2, qx,qy,qz,qs,q);
        fu[ck*4+3] = fkey(R.y, R.z, R.w,  jj+3, qx,qy,qz,qs,q);
    }
    group_bar(g);                      // covers hist zeroing

    // pass 1: histogram on ford bits [31:24]
#pragma unroll
    for (int i = 0; i < 16; i++) atomicAdd(&hist[g][fu[i] >> 24], 1u);
    group_bar(g);
    if (gw == 0) radix_scan(&hist[g][0], lane, KNN, &sB1[g], &sLt[g]);
    group_bar(g);
    unsigned B1 = sB1[g];
    unsigned t2 = KNN - sLt[g];

    // pass 2: refine ford bits [23:16] within bucket B1 (second buffer)
#pragma unroll
    for (int i = 0; i < 16; i++)
        if ((fu[i] >> 24) == B1)
            atomicAdd(&hist[g][256 + ((fu[i] >> 16) & 255u)], 1u);
    group_bar(g);
    if (gw == 0) radix_scan(&hist[g][256], lane, t2, &sB2[g], &sLt2[g]);
    group_bar(g);
    unsigned B2 = sB2[g];

    // collect all keys <= threshold sub-bucket (>=16, typically ~24)
#pragma unroll
    for (int i = 0; i < 16; i++) {
        unsigned b1v = fu[i] >> 24;
        bool take = (b1v < B1) || (b1v == B1 && ((fu[i] >> 16) & 255u) <= B2);
        if (take) {
            int p = atomicAdd(&scand[g], 1);
            cand[g][p] = (((ull)fu[i]) << 11) | (unsigned)(j0 + i);
        }
    }
    group_bar(g);

    // group's warp 0: exact top-16 over the small candidate set
    if (gw == 0) {
        int cnt = scand[g];
        ull res = ~0ULL;
        if (cnt <= 32) {
            // warp bitonic sort of 32 keys; lanes 0..15 = smallest 16, in order
            ull key = (lane < cnt) ? cand[g][lane] : ~0ULL;
#pragma unroll
            for (int k = 2; k <= 32; k <<= 1) {
#pragma unroll
                for (int j = k >> 1; j > 0; j >>= 1) {
                    ull partner = __shfl_xor_sync(0xffffffffu, key, j);
                    bool up    = ((lane & k) == 0);
                    bool lower = ((lane & j) == 0);
                    ull mn = key < partner ? key : partner;
                    ull mx = key < partner ? partner : key;
                    key = (lower == up) ? mn : mx;
                }
            }
            res = key;
        } else {
            for (int r = 0; r < KNN; r++) {
                ull m = ~0ULL; int mp = -1;
                for (int p = lane; p < cnt; p += 32) {
                    ull k = cand[g][p];
                    if (k < m) { m = k; mp = p; }
                }
                ull wm = m;
#pragma unroll
                for (int s = 16; s > 0; s >>= 1) {
                    ull o = __shfl_xor_sync(0xffffffffu, wm, s);
                    wm = o < wm ? o : wm;
                }
                if (m == wm && mp >= 0) cand[g][mp] = ~0ULL;
                __syncwarp();
                if (lane == r) res = wm;
            }
        }
        if (lane < KNN) {
            int j = (int)(res & 0x7FFULL);
            float ax = xb[3*j], ay = xb[3*j+1], az = xb[3*j+2];
            float dx = qx-ax, dy = qy-ay, dz = qz-az;
            g_idx[n*KNN + lane]  = (b << 11) + j;
            g_dist[n*KNN + lane] = sqrtf(dx*dx + dy*dy + dz*dz);
        }
    }
}

// ---------------- fused GEMM (FFMA2, pre-packed weights) --------------------
__global__ __launch_bounds__(256, 4) void gemm_kernel(const float* __restrict__ v) {
    __shared__ float svt[3*CH*8];            // [coord][c][8 points]
    __shared__ float swn[2][4][4][2];
    int p0 = blockIdx.x << 3;
    const float* vb = v + (size_t)p0 * (CH*3);
    for (int i = threadIdx.x; i < 8*CH*3; i += 256) {
        int p = i / 384, r = i % 384;
        int c = r / 3, coord = r % 3;
        svt[coord*1024 + c*8 + p] = vb[i];
    }
    __syncthreads();

    int o    = threadIdx.x & 127;
    int h    = threadIdx.x >> 7;
    int lane = threadIdx.x & 31;
    int w4   = (threadIdx.x >> 5) & 3;
    int h4   = h * 4;

    ull acc[2][3][3];
#pragma unroll
    for (int pr = 0; pr < 2; pr++)
#pragma unroll
        for (int w = 0; w < 3; w++)
#pragma unroll
            for (int d = 0; d < 3; d++) acc[pr][w][d] = 0ULL;

    const ull* wq = g_Wt2 + o;
    const ull* wk = g_Wt2 + CH*CH + o;
    const ull* wu = g_Wt2 + 2*CH*CH + o;

#pragma unroll 4
    for (int c = 0; c < CH; c++) {
        ull aq2 = __ldg(wq + (c << 7));
        ull ak2 = __ldg(wk + (c << 7));
        ull au2 = __ldg(wu + (c << 7));
        ulonglong2 vx = *reinterpret_cast<const ulonglong2*>(&svt[0*1024 + c*8 + h4]);
        ulonglong2 vy = *reinterpret_cast<const ulonglong2*>(&svt[1*1024 + c*8 + h4]);
        ulonglong2 vz = *reinterpret_cast<const ulonglong2*>(&svt[2*1024 + c*8 + h4]);
        acc[0][0][0] = fma2(aq2, vx.x, acc[0][0][0]);
        acc[0][0][1] = fma2(aq2, vy.x, acc[0][0][1]);
        acc[0][0][2] = fma2(aq2, vz.x, acc[0][0][2]);
        acc[0][1][0] = fma2(ak2, vx.x, acc[0][1][0]);
        acc[0][1][1] = fma2(ak2, vy.x, acc[0][1][1]);
        acc[0][1][2] = fma2(ak2, vz.x, acc[0][1][2]);
        acc[0][2][0] = fma2(au2, vx.x, acc[0][2][0]);
        acc[0][2][1] = fma2(au2, vy.x, acc[0][2][1]);
        acc[0][2][2] = fma2(au2, vz.x, acc[0][2][2]);
        acc[1][0][0] = fma2(aq2, vx.y, acc[1][0][0]);
        acc[1][0][1] = fma2(aq2, vy.y, acc[1][0][1]);
        acc[1][0][2] = fma2(aq2, vz.y, acc[1][0][2]);
        acc[1][1][0] = fma2(ak2, vx.y, acc[1][1][0]);
        acc[1][1][1] = fma2(ak2, vy.y, acc[1][1][1]);
        acc[1][1][2] = fma2(ak2, vz.y, acc[1][1][2]);
        acc[1][2][0] = fma2(au2, vx.y, acc[1][2][0]);
        acc[1][2][1] = fma2(au2, vy.y, acc[1][2][1]);
        acc[1][2][2] = fma2(au2, vz.y, acc[1][2][2]);
    }

    float nq[4], nk[4];
#pragma unroll
    for (int pr = 0; pr < 2; pr++) {
        float q0[3], q1[3], k0[3], k1[3], u0[3], u1[3];
#pragma unroll
        for (int d = 0; d < 3; d++) {
            unpack2(acc[pr][0][d], q0[d], q1[d]);
            unpack2(acc[pr][1][d], k0[d], k1[d]);
            unpack2(acc[pr][2][d], u0[d], u1[d]);
        }
        size_t b0 = ((size_t)(p0 + h4 + pr*2 + 0)) * 384 + o;
        size_t b1 = ((size_t)(p0 + h4 + pr*2 + 1)) * 384 + o;
#pragma unroll
        for (int d = 0; d < 3; d++) {
            g_Q[b0 + d*128] = q0[d]; g_Q[b1 + d*128] = q1[d];
            g_K[b0 + d*128] = k0[d]; g_K[b1 + d*128] = k1[d];
            g_U[b0 + d*128] = u0[d]; g_U[b1 + d*128] = u1[d];
        }
        nq[pr*2+0] = sqrtf(q0[0]*q0[0] + q0[1]*q0[1] + q0[2]*q0[2]);
        nq[pr*2+1] = sqrtf(q1[0]*q1[0] + q1[1]*q1[1] + q1[2]*q1[2]);
        nk[pr*2+0] = sqrtf(k0[0]*k0[0] + k0[1]*k0[1] + k0[2]*k0[2]);
        nk[pr*2+1] = sqrtf(k1[0]*k1[0] + k1[1]*k1[1] + k1[2]*k1[2]);
    }
#pragma unroll
    for (int t = 0; t < 4; t++) {
        float vq = nq[t], vk = nk[t];
#pragma unroll
        for (int s = 16; s > 0; s >>= 1) {
            vq += __shfl_xor_sync(0xffffffffu, vq, s);
            vk += __shfl_xor_sync(0xffffffffu, vk, s);
        }
        if (lane == 0) { swn[h][t][w4][0] = vq; swn[h][t][w4][1] = vk; }
    }
    __syncthreads();
    if (threadIdx.x < 16) {
        int h2 = threadIdx.x >> 3, t = (threadIdx.x >> 1) & 3, qk = threadIdx.x & 1;
        float s = swn[h2][t][0][qk] + swn[h2][t][1][qk]
                + swn[h2][t][2][qk] + swn[h2][t][3][qk];
        int pt = p0 + h2*4 + t;
        if (qk == 0) g_qn[pt] = s * (1.f/128.f);
        else         g_kn[pt] = s * (1.f/128.f);
    }
}

// ---------------- fused attention: edge MLP + softmax + message + LN --------
__global__ __launch_bounds__(512) void attn_kernel(
    const float* __restrict__ W1, const float* __restrict__ b1,
    const float* __restrict__ W2, const float* __restrict__ b2,
    const float* __restrict__ W3, const float* __restrict__ b3,
    const float* __restrict__ gamma, const float* __restrict__ beta,
    float* __restrict__ out) {
    int tid  = threadIdx.x;
    int g    = tid >> 7;
    int gtid = tid & 127;
    int lane = tid & 31;
    int gw   = (tid >> 5) & 3;
    int n    = (blockIdx.x << 2) + g;

    __shared__ float sW1t[4*HID];
    __shared__ float sW2t[HID*HID];
    __shared__ float sb1[HID], sb2[HID], sW3[HID];
    __shared__ float sb3;
    __shared__ int   sidx[4][KNN];
    __shared__ float skn[4][KNN], sdist[4][KNN], sdot[4][KNN], satt[4][KNN];
    __shared__ float sqn[4];
    __shared__ float sh2[4][KNN][HID+1];
    __shared__ float sred[4][4];
    __shared__ __align__(16) float sQ[4][CH*3];   // Q row staging; reused for output

    if (tid < 128) {
        int u = tid >> 2, j = tid & 3;
        sW1t[j*HID + u] = W1[tid];
    }
    for (int i = tid; i < HID*HID; i += 512) {
        int u = i >> 5, jj = i & 31;
        sW2t[jj*HID + u] = W2[i];
    }
    if (tid < HID) { sb1[tid] = b1[tid]; sb2[tid] = b2[tid]; sW3[tid] = W3[tid]; }
    if (tid == 0) sb3 = b3[0];
    if (gtid == 0) sqn[g] = g_qn[n];
    if (gtid < KNN) {
        int j = g_idx[n*KNN + gtid];
        sidx[g][gtid]  = j;
        skn[g][gtid]   = g_kn[j];
        sdist[g][gtid] = g_dist[n*KNN + gtid];
    }
    // stage Q row into shared (coalesced)
    {
        const float* Qg = g_Q + (size_t)n*384;
        sQ[g][gtid]     = Qg[gtid];
        sQ[g][gtid+128] = Qg[gtid+128];
        sQ[g][gtid+256] = Qg[gtid+256];
    }
    __syncthreads();

    int ch = gtid;
    float qx = sQ[g][ch], qy = sQ[g][ch+128], qz = sQ[g][ch+256];

    // ---- dot_nbr: warp gw handles neighbors 4*gw..4*gw+3, coalesced rows ----
    {
        const float4* Qp4 = reinterpret_cast<const float4*>(sQ[g]);
#pragma unroll
        for (int kk = 0; kk < 4; kk++) {
            int k = gw*4 + kk;
            const float4* Kp = reinterpret_cast<const float4*>(
                g_K + (size_t)sidx[g][k]*384);
            float d = 0.f;
#pragma unroll
            for (int it = 0; it < 3; it++) {
                float4 a  = Qp4[it*32 + lane];
                float4 bq = Kp[it*32 + lane];
                d = fmaf(a.x, bq.x, d);
                d = fmaf(a.y, bq.y, d);
                d = fmaf(a.z, bq.z, d);
                d = fmaf(a.w, bq.w, d);
            }
#pragma unroll
            for (int s = 16; s > 0; s >>= 1)
                d += __shfl_xor_sync(0xffffffffu, d, s);
            if (lane == 0) sdot[g][k] = d * (1.f/128.f);
        }
    }
    group_bar(g);

    // ---- MLP layer 1: warp gw owns k = gw+4r; h1 kept in registers --------
    float h1r[4];
#pragma unroll
    for (int r = 0; r < 4; r++) {
        int k = gw + 4*r;
        float hv = sb1[lane]
                 + sW1t[0*HID+lane]*sqn[g]
                 + sW1t[1*HID+lane]*skn[g][k]
                 + sW1t[2*HID+lane]*sdot[g][k]
                 + sW1t[3*HID+lane]*sdist[g][k];
        h1r[r] = hv / (1.f + expf(-hv));
    }
    // ---- layer 2: i-outer loop — one w2 LDS serves all 4 neighbors --------
    {
        float hv[4];
#pragma unroll
        for (int r = 0; r < 4; r++) hv[r] = sb2[lane];
#pragma unroll
        for (int i = 0; i < HID; i++) {
            float w2 = sW2t[i*HID+lane];
#pragma unroll
            for (int r = 0; r < 4; r++) {
                float h1i = __shfl_sync(0xffffffffu, h1r[r], i);
                hv[r] = fmaf(w2, h1i, hv[r]);
            }
        }
#pragma unroll
        for (int r = 0; r < 4; r++) {
            int k = gw + 4*r;
            sh2[g][k][lane] = hv[r] / (1.f + expf(-hv[r]));
        }
    }
    group_bar(g);
    // ---- layer 3 + clip + softmax in group's warp 0 ----
    if (gw == 0) {
        float l = -INFINITY;
        if (lane < KNN) {
            float t = sb3;
#pragma unroll
            for (int i = 0; i < HID; i++) t = fmaf(sW3[i], sh2[g][lane][i], t);
            l = fminf(fmaxf(t, -10.f), 10.f);
        }
        float mx = l;
#pragma unroll
        for (int s = 8; s > 0; s >>= 1)
            mx = fmaxf(mx, __shfl_xor_sync(0xffffffffu, mx, s));
        float e = (lane < KNN) ? expf(l - mx) : 0.f;
        float sum = e;
#pragma unroll
        for (int s = 8; s > 0; s >>= 1) sum += __shfl_xor_sync(0xffffffffu, sum, s);
        if (lane < KNN) satt[g][lane] = e / sum;
    }
    group_bar(g);

    // ---- message (SoA coalesced gathers) ----
    float mxs = 0.f, mys = 0.f, mzs = 0.f;
#pragma unroll
    for (int k = 0; k < KNN; k++) {
        const float* Up = g_U + (size_t)sidx[g][k]*384 + ch;
        float a = satt[g][k];
        mxs = fmaf(a, Up[0],   mxs);
        mys = fmaf(a, Up[128], mys);
        mzs = fmaf(a, Up[256], mzs);
    }
    float ox = qx + 0.5f*mxs;
    float oy = qy + 0.5f*mys;
    float oz = qz + 0.5f*mzs;

    // ---- vn layer norm ----
    float nrm = fmaxf(sqrtf(ox*ox + oy*oy + oz*oz), EPSV);
    float vv = nrm;
#pragma unroll
    for (int s = 16; s > 0; s >>= 1) vv += __shfl_xor_sync(0xffffffffu, vv, s);
    if (lane == 0) sred[g][gw] = vv;
    group_bar(g);
    float mean = (sred[g][0]+sred[g][1]+sred[g][2]+sred[g][3]) * (1.f/128.f);
    group_bar(g);
    float dev = nrm - mean;
    vv = dev*dev;
#pragma unroll
    for (int s = 16; s > 0; s >>= 1) vv += __shfl_xor_sync(0xffffffffu, vv, s);
    if (lane == 0) sred[g][gw] = vv;
    group_bar(g);
    float stdv = fmaxf(sqrtf((sred[g][0]+sred[g][1]+sred[g][2]+sred[g][3]) * (1.f/127.f)), EPSV);
    float ns = (dev/stdv)*gamma[ch] + beta[ch];
    float sc = fmaxf(ns, EPSV) / nrm;
    ox *= sc; oy *= sc; oz *= sc;

    float n2 = fmaxf(sqrtf(ox*ox + oy*oy + oz*oz), EPSV);
    float cl = fminf(50.f/n2, 1.f);

    // ---- stage AoS output in sQ (done with Q row), coalesced global store ----
    group_bar(g);
    sQ[g][ch*3+0] = ox*cl;
    sQ[g][ch*3+1] = oy*cl;
    sQ[g][ch*3+2] = oz*cl;
    group_bar(g);
    float* ob = out + (size_t)n*384;
#pragma unroll
    for (int d = 0; d < 3; d++) ob[d*128 + gtid] = sQ[g][d*128 + gtid];
}

// ---------------- launch ----------------------------------------------------
extern "C" void kernel_launch(void* const* d_in, const int* in_sizes, int n_in,
                              void* d_out, int out_size) {
    const float* x     = (const float*)d_in[0];
    const float* v     = (const float*)d_in[1];
    const float* Wq    = (const float*)d_in[2];
    const float* Wk    = (const float*)d_in[3];
    const float* Wu    = (const float*)d_in[4];
    const float* W1    = (const float*)d_in[5];
    const float* b1    = (const float*)d_in[6];
    const float* W2    = (const float*)d_in[7];
    const float* b2    = (const float*)d_in[8];
    const float* W3    = (const float*)d_in[9];
    const float* b3    = (const float*)d_in[10];
    const float* gamma = (const float*)d_in[11];
    const float* beta  = (const float*)d_in[12];
    float* out = (float*)d_out;

    transpose_w_kernel<<<64, 256>>>(Wq, Wk, Wu);  // idx 0
    gemm_kernel<<<2048, 256>>>(v);                // idx 1
    knn_kernel<<<NTOT/2, 256>>>(x);               // idx 2
    attn_kernel<<<NTOT/4, 512>>>(W1, b1, W2, b2, W3, b3, gamma, beta, out);  // idx 3 <- profiled
}

// round 16
// speedup vs baseline: 1.0384x; 1.0384x over previous
#include <cuda_runtime.h>
#include <math.h>

#define BATCH 8
#define NPTS 2048
#define NTOT (BATCH*NPTS)
#define CH 128
#define KNN 16
#define HID 32
#define EPSV 1e-6f

typedef unsigned long long ull;

// ---------------- scratch (static device globals) ---------------------------
// SoA layout: [point][coord][128 channels]
__device__ float g_Q[NTOT*CH*3];
__device__ float g_K[NTOT*CH*3];
__device__ float g_U[NTOT*CH*3];
__device__ float g_Wt[3*CH*CH];      // transposed weights, layout [w][c][o]
__device__ int   g_idx[NTOT*KNN];
__device__ float g_dist[NTOT*KNN];
__device__ float g_qn[NTOT];
__device__ float g_kn[NTOT];

// ---------------- packed f32x2 helpers (Blackwell FFMA2) --------------------
__device__ __forceinline__ ull pack2(float lo, float hi) {
    ull r;
    asm("mov.b64 %0, {%1,%2};" : "=l"(r) : "f"(lo), "f"(hi));
    return r;
}
__device__ __forceinline__ void unpack2(ull v, float& lo, float& hi) {
    asm("mov.b64 {%0,%1}, %2;" : "=f"(lo), "=f"(hi) : "l"(v));
}
__device__ __forceinline__ ull fma2(ull a, ull b, ull c) {
    ull d;
    asm("fma.rn.f32x2 %0, %1, %2, %3;" : "=l"(d) : "l"(a), "l"(b), "l"(c));
    return d;
}
__device__ __forceinline__ void group_bar(int g) {
    asm volatile("bar.sync %0, 128;" :: "r"(g + 1) : "memory");
}
// monotone float->uint transform
__device__ __forceinline__ unsigned ford(float f) {
    unsigned u = __float_as_uint(f);
    return u ^ ((unsigned)(((int)u) >> 31) | 0x80000000u);
}

// ---------------- weight transpose ------------------------------------------
__global__ void transpose_w_kernel(const float* __restrict__ Wq,
                                   const float* __restrict__ Wk,
                                   const float* __restrict__ Wu) {
    int i = blockIdx.x * 256 + threadIdx.x;       // i = o*128 + c
    if (i >= CH*CH) return;
    int o = i >> 7, c = i & 127;
    g_Wt[0*CH*CH + c*CH + o] = Wq[i];
    g_Wt[1*CH*CH + c*CH + o] = Wk[i];
    g_Wt[2*CH*CH + c*CH + o] = Wu[i];
}

// ---------------- KNN: radix-select, 2 queries/block, bitonic tail ----------
__device__ __forceinline__ unsigned fkey(float ax, float ay, float az, int j,
                                         float qx, float qy, float qz,
                                         float qs, int q) {
    float sj  = ax*ax + ay*ay + az*az;
    float dot = qx*ax + qy*ay + qz*az;
    float d2  = (qs + sj) - 2.f*dot;
    if (j == q) d2 = INFINITY;
    return ford(d2);
}

// warp-0-of-group only: smallest bin with cum_incl >= target over 256 bins.
__device__ __forceinline__ void radix_scan(const unsigned* hist, int lane,
                                           unsigned target,
                                           unsigned* outB, unsigned* outLt) {
    unsigned c[8]; unsigned s = 0;
#pragma unroll
    for (int i = 0; i < 8; i++) { c[i] = hist[lane*8 + i]; s += c[i]; }
    unsigned pre = s;
#pragma unroll
    for (int d = 1; d < 32; d <<= 1) {
        unsigned o = __shfl_up_sync(0xffffffffu, pre, d);
        if (lane >= d) pre += o;
    }
    unsigned excl = pre - s;
    bool has = (excl < target) && (excl + s >= target);
    unsigned mask = __ballot_sync(0xffffffffu, has);
    int src = __ffs((int)mask) - 1;
    if (lane == src) {
        unsigned cum = excl, lt = excl; int bsel = lane*8;
#pragma unroll
        for (int i = 0; i < 8; i++) {
            if (cum < target) { bsel = lane*8 + i; lt = cum; cum += c[i]; }
        }
        *outB = (unsigned)bsel; *outLt = lt;
    }
}

__global__ __launch_bounds__(256) void knn_kernel(const float* __restrict__ x) {
    int tid  = threadIdx.x;
    int g    = tid >> 7;              // query group 0/1
    int gtid = tid & 127;
    int lane = tid & 31;
    int gw   = (tid >> 5) & 3;
    int n    = (blockIdx.x << 1) + g;
    int b    = n >> 11;
    int q    = n & 2047;
    const float* xb = x + (size_t)b * NPTS * 3;

    __shared__ unsigned hist[2][512];  // [g][pass1:0-255 | pass2:256-511]
    __shared__ ull cand[2][NPTS];
    __shared__ int scand[2];
    __shared__ unsigned sB1[2], sLt[2], sB2[2], sLt2[2];

    hist[g][gtid] = 0; hist[g][gtid+128] = 0;
    hist[g][gtid+256] = 0; hist[g][gtid+384] = 0;
    if (gtid == 0) scand[g] = 0;

    float qx = xb[3*q+0], qy = xb[3*q+1], qz = xb[3*q+2];
    float qs = qx*qx + qy*qy + qz*qz;

    int j0 = gtid * 16;
    const float4* xp4 = reinterpret_cast<const float4*>(xb + (size_t)j0 * 3);
    unsigned fu[16];
#pragma unroll
    for (int ck = 0; ck < 4; ck++) {
        float4 P = xp4[ck*3+0], Qv = xp4[ck*3+1], R = xp4[ck*3+2];
        int jj = j0 + ck*4;
        fu[ck*4+0] = fkey(P.x, P.y, P.z,  jj+0, qx,qy,qz,qs,q);
        fu[ck*4+1] = fkey(P.w, Qv.x, Qv.y, jj+1, qx,qy,qz,qs,q);
        fu[ck*4+2] = fkey(Qv.z, Qv.w, R.x, jj+2, qx,qy,qz,qs,q);
        fu[ck*4+3] = fkey(R.y, R.z, R.w,  jj+3, qx,qy,qz,qs,q);
    }
    group_bar(g);

    // pass 1: histogram on ford bits [31:24]
#pragma unroll
    for (int i = 0; i < 16; i++) atomicAdd(&hist[g][fu[i] >> 24], 1u);
    group_bar(g);
    if (gw == 0) radix_scan(&hist[g][0], lane, KNN, &sB1[g], &sLt[g]);
    group_bar(g);
    unsigned B1 = sB1[g];
    unsigned t2 = KNN - sLt[g];

    // pass 2: refine ford bits [23:16] within bucket B1
#pragma unroll
    for (int i = 0; i < 16; i++)
        if ((fu[i] >> 24) == B1)
            atomicAdd(&hist[g][256 + ((fu[i] >> 16) & 255u)], 1u);
    group_bar(g);
    if (gw == 0) radix_scan(&hist[g][256], lane, t2, &sB2[g], &sLt2[g]);
    group_bar(g);
    unsigned B2 = sB2[g];

    // collect all keys <= threshold sub-bucket
#pragma unroll
    for (int i = 0; i < 16; i++) {
        unsigned b1v = fu[i] >> 24;
        bool take = (b1v < B1) || (b1v == B1 && ((fu[i] >> 16) & 255u) <= B2);
        if (take) {
            int p = atomicAdd(&scand[g], 1);
            cand[g][p] = (((ull)fu[i]) << 11) | (unsigned)(j0 + i);
        }
    }
    group_bar(g);

    if (gw == 0) {
        int cnt = scand[g];
        ull res = ~0ULL;
        if (cnt <= 32) {
            ull key = (lane < cnt) ? cand[g][lane] : ~0ULL;
#pragma unroll
            for (int k = 2; k <= 32; k <<= 1) {
#pragma unroll
                for (int j = k >> 1; j > 0; j >>= 1) {
                    ull partner = __shfl_xor_sync(0xffffffffu, key, j);
                    bool up    = ((lane & k) == 0);
                    bool lower = ((lane & j) == 0);
                    ull mn = key < partner ? key : partner;
                    ull mx = key < partner ? partner : key;
                    key = (lower == up) ? mn : mx;
                }
            }
            res = key;
        } else {
            for (int r = 0; r < KNN; r++) {
                ull m = ~0ULL; int mp = -1;
                for (int p = lane; p < cnt; p += 32) {
                    ull k = cand[g][p];
                    if (k < m) { m = k; mp = p; }
                }
                ull wm = m;
#pragma unroll
                for (int s = 16; s > 0; s >>= 1) {
                    ull o = __shfl_xor_sync(0xffffffffu, wm, s);
                    wm = o < wm ? o : wm;
                }
                if (m == wm && mp >= 0) cand[g][mp] = ~0ULL;
                __syncwarp();
                if (lane == r) res = wm;
            }
        }
        if (lane < KNN) {
            int j = (int)(res & 0x7FFULL);
            float ax = xb[3*j], ay = xb[3*j+1], az = xb[3*j+2];
            float dx = qx-ax, dy = qy-ay, dz = qz-az;
            g_idx[n*KNN + lane]  = (b << 11) + j;
            g_dist[n*KNN + lane] = sqrtf(dx*dx + dy*dy + dz*dz);
        }
    }
}

// ---------------- fused GEMM (FFMA2, in-loop pack — R14 winner) -------------
__global__ __launch_bounds__(256, 4) void gemm_kernel(const float* __restrict__ v) {
    __shared__ float svt[3*CH*8];            // [coord][c][8 points]
    __shared__ float swn[2][4][4][2];
    int p0 = blockIdx.x << 3;
    const float* vb = v + (size_t)p0 * (CH*3);
    for (int i = threadIdx.x; i < 8*CH*3; i += 256) {
        int p = i / 384, r = i % 384;
        int c = r / 3, coord = r % 3;
        svt[coord*1024 + c*8 + p] = vb[i];
    }
    __syncthreads();

    int o    = threadIdx.x & 127;
    int h    = threadIdx.x >> 7;
    int lane = threadIdx.x & 31;
    int w4   = (threadIdx.x >> 5) & 3;
    int h4   = h * 4;

    ull acc[2][3][3];
#pragma unroll
    for (int pr = 0; pr < 2; pr++)
#pragma unroll
        for (int w = 0; w < 3; w++)
#pragma unroll
            for (int d = 0; d < 3; d++) acc[pr][w][d] = 0ULL;

    const float* wq = g_Wt + o;
    const float* wk = g_Wt + CH*CH + o;
    const float* wu = g_Wt + 2*CH*CH + o;

#pragma unroll 4
    for (int c = 0; c < CH; c++) {
        float aq = __ldg(wq + (c << 7));
        float ak = __ldg(wk + (c << 7));
        float au = __ldg(wu + (c << 7));
        ull aq2 = pack2(aq, aq), ak2 = pack2(ak, ak), au2 = pack2(au, au);
        ulonglong2 vx = *reinterpret_cast<const ulonglong2*>(&svt[0*1024 + c*8 + h4]);
        ulonglong2 vy = *reinterpret_cast<const ulonglong2*>(&svt[1*1024 + c*8 + h4]);
        ulonglong2 vz = *reinterpret_cast<const ulonglong2*>(&svt[2*1024 + c*8 + h4]);
        acc[0][0][0] = fma2(aq2, vx.x, acc[0][0][0]);
        acc[0][0][1] = fma2(aq2, vy.x, acc[0][0][1]);
        acc[0][0][2] = fma2(aq2, vz.x, acc[0][0][2]);
        acc[0][1][0] = fma2(ak2, vx.x, acc[0][1][0]);
        acc[0][1][1] = fma2(ak2, vy.x, acc[0][1][1]);
        acc[0][1][2] = fma2(ak2, vz.x, acc[0][1][2]);
        acc[0][2][0] = fma2(au2, vx.x, acc[0][2][0]);
        acc[0][2][1] = fma2(au2, vy.x, acc[0][2][1]);
        acc[0][2][2] = fma2(au2, vz.x, acc[0][2][2]);
        acc[1][0][0] = fma2(aq2, vx.y, acc[1][0][0]);
        acc[1][0][1] = fma2(aq2, vy.y, acc[1][0][1]);
        acc[1][0][2] = fma2(aq2, vz.y, acc[1][0][2]);
        acc[1][1][0] = fma2(ak2, vx.y, acc[1][1][0]);
        acc[1][1][1] = fma2(ak2, vy.y, acc[1][1][1]);
        acc[1][1][2] = fma2(ak2, vz.y, acc[1][1][2]);
        acc[1][2][0] = fma2(au2, vx.y, acc[1][2][0]);
        acc[1][2][1] = fma2(au2, vy.y, acc[1][2][1]);
        acc[1][2][2] = fma2(au2, vz.y, acc[1][2][2]);
    }

    float nq[4], nk[4];
#pragma unroll
    for (int pr = 0; pr < 2; pr++) {
        float q0[3], q1[3], k0[3], k1[3], u0[3], u1[3];
#pragma unroll
        for (int d = 0; d < 3; d++) {
            unpack2(acc[pr][0][d], q0[d], q1[d]);
            unpack2(acc[pr][1][d], k0[d], k1[d]);
            unpack2(acc[pr][2][d], u0[d], u1[d]);
        }
        size_t b0 = ((size_t)(p0 + h4 + pr*2 + 0)) * 384 + o;
        size_t b1 = ((size_t)(p0 + h4 + pr*2 + 1)) * 384 + o;
#pragma unroll
        for (int d = 0; d < 3; d++) {
            g_Q[b0 + d*128] = q0[d]; g_Q[b1 + d*128] = q1[d];
            g_K[b0 + d*128] = k0[d]; g_K[b1 + d*128] = k1[d];
            g_U[b0 + d*128] = u0[d]; g_U[b1 + d*128] = u1[d];
        }
        nq[pr*2+0] = sqrtf(q0[0]*q0[0] + q0[1]*q0[1] + q0[2]*q0[2]);
        nq[pr*2+1] = sqrtf(q1[0]*q1[0] + q1[1]*q1[1] + q1[2]*q1[2]);
        nk[pr*2+0] = sqrtf(k0[0]*k0[0] + k0[1]*k0[1] + k0[2]*k0[2]);
        nk[pr*2+1] = sqrtf(k1[0]*k1[0] + k1[1]*k1[1] + k1[2]*k1[2]);
    }
#pragma unroll
    for (int t = 0; t < 4; t++) {
        float vq = nq[t], vk = nk[t];
#pragma unroll
        for (int s = 16; s > 0; s >>= 1) {
            vq += __shfl_xor_sync(0xffffffffu, vq, s);
            vk += __shfl_xor_sync(0xffffffffu, vk, s);
        }
        if (lane == 0) { swn[h][t][w4][0] = vq; swn[h][t][w4][1] = vk; }
    }
    __syncthreads();
    if (threadIdx.x < 16) {
        int h2 = threadIdx.x >> 3, t = (threadIdx.x >> 1) & 3, qk = threadIdx.x & 1;
        float s = swn[h2][t][0][qk] + swn[h2][t][1][qk]
                + swn[h2][t][2][qk] + swn[h2][t][3][qk];
        int pt = p0 + h2*4 + t;
        if (qk == 0) g_qn[pt] = s * (1.f/128.f);
        else         g_kn[pt] = s * (1.f/128.f);
    }
}

// ---------------- fused attention (R14 base + one-pass LN + sout) -----------
__global__ __launch_bounds__(512) void attn_kernel(
    const float* __restrict__ W1, const float* __restrict__ b1,
    const float* __restrict__ W2, const float* __restrict__ b2,
    const float* __restrict__ W3, const float* __restrict__ b3,
    const float* __restrict__ gamma, const float* __restrict__ beta,
    float* __restrict__ out) {
    int tid  = threadIdx.x;
    int g    = tid >> 7;
    int gtid = tid & 127;
    int lane = tid & 31;
    int gw   = (tid >> 5) & 3;
    int n    = (blockIdx.x << 2) + g;

    __shared__ float sW1t[4*HID];
    __shared__ float sW2t[HID*HID];
    __shared__ float sb1[HID], sb2[HID], sW3[HID];
    __shared__ float sb3;
    __shared__ int   sidx[4][KNN];
    __shared__ float skn[4][KNN], sdist[4][KNN], sdot[4][KNN], satt[4][KNN];
    __shared__ float sqn[4];
    __shared__ float sh2[4][KNN][HID+1];
    __shared__ float sred[4][4][2];                // [g][warp][sum|sumsq]
    __shared__ __align__(16) float sQ[4][CH*3];    // Q row staging
    __shared__ float sout[4][CH*3];                // output staging

    if (tid < 128) {
        int u = tid >> 2, j = tid & 3;
        sW1t[j*HID + u] = W1[tid];
    }
    for (int i = tid; i < HID*HID; i += 512) {
        int u = i >> 5, jj = i & 31;
        sW2t[jj*HID + u] = W2[i];
    }
    if (tid < HID) { sb1[tid] = b1[tid]; sb2[tid] = b2[tid]; sW3[tid] = W3[tid]; }
    if (tid == 0) sb3 = b3[0];
    if (gtid == 0) sqn[g] = g_qn[n];
    if (gtid < KNN) {
        int j = g_idx[n*KNN + gtid];
        sidx[g][gtid]  = j;
        skn[g][gtid]   = g_kn[j];
        sdist[g][gtid] = g_dist[n*KNN + gtid];
    }
    {
        const float* Qg = g_Q + (size_t)n*384;
        sQ[g][gtid]     = Qg[gtid];
        sQ[g][gtid+128] = Qg[gtid+128];
        sQ[g][gtid+256] = Qg[gtid+256];
    }
    __syncthreads();

    int ch = gtid;
    float qx = sQ[g][ch], qy = sQ[g][ch+128], qz = sQ[g][ch+256];

    // ---- dot_nbr: warp gw handles neighbors 4*gw..4*gw+3, coalesced rows ----
    {
        const float4* Qp4 = reinterpret_cast<const float4*>(sQ[g]);
#pragma unroll
        for (int kk = 0; kk < 4; kk++) {
            int k = gw*4 + kk;
            const float4* Kp = reinterpret_cast<const float4*>(
                g_K + (size_t)sidx[g][k]*384);
            float d = 0.f;
#pragma unroll
            for (int it = 0; it < 3; it++) {
                float4 a  = Qp4[it*32 + lane];
                float4 bq = Kp[it*32 + lane];
                d = fmaf(a.x, bq.x, d);
                d = fmaf(a.y, bq.y, d);
                d = fmaf(a.z, bq.z, d);
                d = fmaf(a.w, bq.w, d);
            }
#pragma unroll
            for (int s = 16; s > 0; s >>= 1)
                d += __shfl_xor_sync(0xffffffffu, d, s);
            if (lane == 0) sdot[g][k] = d * (1.f/128.f);
        }
    }
    group_bar(g);

    // ---- MLP layer 1: warp gw owns k = gw+4r; h1 kept in registers --------
    float h1r[4];
#pragma unroll
    for (int r = 0; r < 4; r++) {
        int k = gw + 4*r;
        float hv = sb1[lane]
                 + sW1t[0*HID+lane]*sqn[g]
                 + sW1t[1*HID+lane]*skn[g][k]
                 + sW1t[2*HID+lane]*sdot[g][k]
                 + sW1t[3*HID+lane]*sdist[g][k];
        h1r[r] = hv / (1.f + expf(-hv));
    }
    // ---- layer 2: h1 broadcast via shfl ----
#pragma unroll
    for (int r = 0; r < 4; r++) {
        int k = gw + 4*r;
        float hv = sb2[lane];
#pragma unroll
        for (int i = 0; i < HID; i++) {
            float h1i = __shfl_sync(0xffffffffu, h1r[r], i);
            hv = fmaf(sW2t[i*HID+lane], h1i, hv);
        }
        sh2[g][k][lane] = hv / (1.f + expf(-hv));
    }
    group_bar(g);
    // ---- layer 3 + clip + softmax in group's warp 0 ----
    if (gw == 0) {
        float l = -INFINITY;
        if (lane < KNN) {
            float t = sb3;
#pragma unroll
            for (int i = 0; i < HID; i++) t = fmaf(sW3[i], sh2[g][lane][i], t);
            l = fminf(fmaxf(t, -10.f), 10.f);
        }
        float mx = l;
#pragma unroll
        for (int s = 8; s > 0; s >>= 1)
            mx = fmaxf(mx, __shfl_xor_sync(0xffffffffu, mx, s));
        float e = (lane < KNN) ? expf(l - mx) : 0.f;
        float sum = e;
#pragma unroll
        for (int s = 8; s > 0; s >>= 1) sum += __shfl_xor_sync(0xffffffffu, sum, s);
        if (lane < KNN) satt[g][lane] = e / sum;
    }
    group_bar(g);

    // ---- message (SoA coalesced gathers) ----
    float mxs = 0.f, mys = 0.f, mzs = 0.f;
#pragma unroll
    for (int k = 0; k < KNN; k++) {
        const float* Up = g_U + (size_t)sidx[g][k]*384 + ch;
        float a = satt[g][k];
        mxs = fmaf(a, Up[0],   mxs);
        mys = fmaf(a, Up[128], mys);
        mzs = fmaf(a, Up[256], mzs);
    }
    float ox = qx + 0.5f*mxs;
    float oy = qy + 0.5f*mys;
    float oz = qz + 0.5f*mzs;

    // ---- vn layer norm: one-pass (sum, sumsq) reduction --------------------
    float nrm = fmaxf(sqrtf(ox*ox + oy*oy + oz*oz), EPSV);
    float s1 = nrm, s2 = nrm*nrm;
#pragma unroll
    for (int s = 16; s > 0; s >>= 1) {
        s1 += __shfl_xor_sync(0xffffffffu, s1, s);
        s2 += __shfl_xor_sync(0xffffffffu, s2, s);
    }
    if (lane == 0) { sred[g][gw][0] = s1; sred[g][gw][1] = s2; }
    group_bar(g);
    float sum1 = sred[g][0][0]+sred[g][1][0]+sred[g][2][0]+sred[g][3][0];
    float sum2 = sred[g][0][1]+sred[g][1][1]+sred[g][2][1]+sred[g][3][1];
    float mean = sum1 * (1.f/128.f);
    float var  = (sum2 - 128.f*mean*mean) * (1.f/127.f);
    float stdv = fmaxf(sqrtf(fmaxf(var, 0.f)), EPSV);
    float dev  = nrm - mean;
    float ns = (dev/stdv)*gamma[ch] + beta[ch];
    float sc = fmaxf(ns, EPSV) / nrm;
    ox *= sc; oy *= sc; oz *= sc;

    float n2 = fmaxf(sqrtf(ox*ox + oy*oy + oz*oz), EPSV);
    float cl = fminf(50.f/n2, 1.f);

    // ---- stage AoS output in dedicated sout, coalesced global store --------
    sout[g][ch*3+0] = ox*cl;
    sout[g][ch*3+1] = oy*cl;
    sout[g][ch*3+2] = oz*cl;
    group_bar(g);
    float* ob = out + (size_t)n*384;
#pragma unroll
    for (int d = 0; d < 3; d++) ob[d*128 + gtid] = sout[g][d*128 + gtid];
}

// ---------------- launch ----------------------------------------------------
extern "C" void kernel_launch(void* const* d_in, const int* in_sizes, int n_in,
                              void* d_out, int out_size) {
    const float* x     = (const float*)d_in[0];
    const float* v     = (const float*)d_in[1];
    const float* Wq    = (const float*)d_in[2];
    const float* Wk    = (const float*)d_in[3];
    const float* Wu    = (const float*)d_in[4];
    const float* W1    = (const float*)d_in[5];
    const float* b1    = (const float*)d_in[6];
    const float* W2    = (const float*)d_in[7];
    const float* b2    = (const float*)d_in[8];
    const float* W3    = (const float*)d_in[9];
    const float* b3    = (const float*)d_in[10];
    const float* gamma = (const float*)d_in[11];
    const float* beta  = (const float*)d_in[12];
    float* out = (float*)d_out;

    transpose_w_kernel<<<64, 256>>>(Wq, Wk, Wu);  // idx 0
    gemm_kernel<<<2048, 256>>>(v);                // idx 1
    knn_kernel<<<NTOT/2, 256>>>(x);               // idx 2
    attn_kernel<<<NTOT/4, 512>>>(W1, b1, W2, b2, W3, b3, gamma, beta, out);  // idx 3 <- profiled
}